// round 6
// baseline (speedup 1.0000x reference)
#include <cuda_runtime.h>
#include <cuda_fp16.h>
#include <math.h>

#define NN 100000
#define EE 1600000

// ---------------- static device scratch ----------------
__device__ float g_bufA[NN * 64];     // GEMM output as __half
__device__ float g_bufB[NN * 64];     // agg output as __half (layers 1,2)
__device__ int   g_csr[EE];
__device__ int   g_rowptr[NN + 1];
__device__ int   g_next[NN];
__device__ int   g_counts[NN];
__device__ float g_dinv[NN];
__device__ float g_stat[4 * 64];      // [sum1, sq1, sum2, sq2]
__device__ int   g_bsum[1024];
__device__ int   g_boff[1024];

// ---------------- packed f32x2 helpers ----------------
__device__ __forceinline__ unsigned long long pack2(float x, float y) {
    unsigned long long r;
    asm("mov.b64 %0, {%1, %2};" : "=l"(r) : "f"(x), "f"(y));
    return r;
}
__device__ __forceinline__ unsigned long long pack2s(float x) {
    unsigned long long r;
    asm("mov.b64 %0, {%1, %1};" : "=l"(r) : "f"(x));
    return r;
}
__device__ __forceinline__ void unpack2(unsigned long long v, float& x, float& y) {
    asm("mov.b64 {%0, %1}, %2;" : "=f"(x), "=f"(y) : "l"(v));
}
__device__ __forceinline__ void ffma2(unsigned long long& a, unsigned long long x,
                                      unsigned long long w) {
#if defined(__CUDA_ARCH__) && (__CUDA_ARCH__ >= 1000)
    asm("fma.rn.f32x2 %0, %1, %2, %0;" : "+l"(a) : "l"(x), "l"(w));
#else
    float ax, ay, xx, xy, wx, wy;
    unpack2(a, ax, ay); unpack2(x, xx, xy); unpack2(w, wx, wy);
    a = pack2(fmaf(xx, wx, ax), fmaf(xy, wy, ay));
#endif
}

// ---------------- zero counts + BN stats ----------------
__global__ void zero_kernel(int* counts, float* stat, int n) {
    int i = blockIdx.x * blockDim.x + threadIdx.x;
    if (i < n) counts[i] = 0;
    if (i < 4 * 64) stat[i] = 0.0f;
}

// ---------------- count in-degree (4 edges/thread, int4 loads) ----------------
__global__ void count_kernel(const int* __restrict__ dst, int* counts, int e) {
    int i = (blockIdx.x * blockDim.x + threadIdx.x) * 4;
    if (i + 4 <= e) {
        int4 d = *reinterpret_cast<const int4*>(&dst[i]);
        atomicAdd(&counts[d.x], 1);
        atomicAdd(&counts[d.y], 1);
        atomicAdd(&counts[d.z], 1);
        atomicAdd(&counts[d.w], 1);
    } else {
        for (; i < e; i++) atomicAdd(&counts[dst[i]], 1);
    }
}

// ---------------- two-level scan ----------------
__global__ void bsum_kernel(const int* __restrict__ counts, int* bsum, int n) {
    __shared__ int sh[8];
    int base = blockIdx.x * 1024;
    int t = threadIdx.x;
    int s = 0;
    #pragma unroll
    for (int j = 0; j < 4; j++) {
        int i = base + t + j * 256;
        if (i < n) s += counts[i];
    }
    #pragma unroll
    for (int o = 16; o > 0; o >>= 1) s += __shfl_xor_sync(0xFFFFFFFFu, s, o);
    if ((t & 31) == 0) sh[t >> 5] = s;
    __syncthreads();
    if (t == 0) {
        int tot = 0;
        #pragma unroll
        for (int w = 0; w < 8; w++) tot += sh[w];
        bsum[blockIdx.x] = tot;
    }
}

__global__ void bscan_kernel(const int* __restrict__ bsum, int* boff, int* rowptr,
                             int nb, int n, int e) {
    __shared__ int sh[4];
    __shared__ int carry_s;
    int t = threadIdx.x;
    if (t == 0) carry_s = 0;
    __syncthreads();
    for (int base = 0; base < nb; base += 128) {
        int i = base + t;
        int v = (i < nb) ? bsum[i] : 0;
        int incl = v;
        #pragma unroll
        for (int o = 1; o < 32; o <<= 1) {
            int u = __shfl_up_sync(0xFFFFFFFFu, incl, o);
            if ((t & 31) >= o) incl += u;
        }
        if ((t & 31) == 31) sh[t >> 5] = incl;
        __syncthreads();
        int wadd = 0;
        for (int w = 0; w < (t >> 5); w++) wadd += sh[w];
        int c = carry_s;
        if (i < nb) boff[i] = c + wadd + incl - v;
        __syncthreads();
        if (t == 127) carry_s = c + wadd + incl;
        __syncthreads();
    }
    if (t == 0) rowptr[n] = e;
}

__global__ void scatter_scan_kernel(const int* __restrict__ counts,
                                    const int* __restrict__ boff,
                                    int* rowptr, int* nextp, float* dinv, int n) {
    __shared__ int sh[8];
    int t = threadIdx.x;
    int i0 = blockIdx.x * 1024 + t * 4;
    int c0 = 0, c1 = 0, c2 = 0, c3 = 0;
    if (i0     < n) c0 = counts[i0];
    if (i0 + 1 < n) c1 = counts[i0 + 1];
    if (i0 + 2 < n) c2 = counts[i0 + 2];
    if (i0 + 3 < n) c3 = counts[i0 + 3];
    int tot = c0 + c1 + c2 + c3;
    int incl = tot;
    #pragma unroll
    for (int o = 1; o < 32; o <<= 1) {
        int u = __shfl_up_sync(0xFFFFFFFFu, incl, o);
        if ((t & 31) >= o) incl += u;
    }
    if ((t & 31) == 31) sh[t >> 5] = incl;
    __syncthreads();
    int wadd = 0;
    for (int w = 0; w < (t >> 5); w++) wadd += sh[w];
    int off = boff[blockIdx.x] + wadd + incl - tot;
    if (i0 < n)     { rowptr[i0]   = off; nextp[i0]   = off; dinv[i0]   = rsqrtf((float)(c0 + 1)); }
    off += c0;
    if (i0 + 1 < n) { rowptr[i0+1] = off; nextp[i0+1] = off; dinv[i0+1] = rsqrtf((float)(c1 + 1)); }
    off += c1;
    if (i0 + 2 < n) { rowptr[i0+2] = off; nextp[i0+2] = off; dinv[i0+2] = rsqrtf((float)(c2 + 1)); }
    off += c2;
    if (i0 + 3 < n) { rowptr[i0+3] = off; nextp[i0+3] = off; dinv[i0+3] = rsqrtf((float)(c3 + 1)); }
}

// ---------------- scatter edges into CSR by dst (4 edges/thread) ----------------
__global__ void fill_kernel(const int* __restrict__ src, const int* __restrict__ dst,
                            int* nextp, int* csr, int e) {
    int i = (blockIdx.x * blockDim.x + threadIdx.x) * 4;
    if (i + 4 <= e) {
        int4 d = *reinterpret_cast<const int4*>(&dst[i]);
        int4 s = *reinterpret_cast<const int4*>(&src[i]);
        csr[atomicAdd(&nextp[d.x], 1)] = s.x;
        csr[atomicAdd(&nextp[d.y], 1)] = s.y;
        csr[atomicAdd(&nextp[d.z], 1)] = s.z;
        csr[atomicAdd(&nextp[d.w], 1)] = s.w;
    } else {
        for (; i < e; i++) {
            int p = atomicAdd(&nextp[dst[i]], 1);
            csr[p] = src[i];
        }
    }
}

// ---------------- GEMM: Yh[r,:] = half(sc_r * (act(X)[r,:] @ W^T + b)) ----------
// 128-row tiles, 8 warps; lane owns rows lane+{0,32,64,96}; warp w owns 8 outputs.
// W broadcast-reads amortized over 4 rows: per 4 k's a warp does
// 4 X-LDS.128 + 8 W-LDS.128 feeding 64 FFMA2.
template <int CIN, bool BN, bool PRESCALE, typename TIN>
__global__ __launch_bounds__(256)
void gemm_kernel(const TIN* __restrict__ X, const float* __restrict__ W,
                 const float* __restrict__ bias,
                 const float* __restrict__ stat, const float* __restrict__ gam,
                 const float* __restrict__ bet, float invn,
                 const float* __restrict__ dinv,
                 __half* __restrict__ Yh, int n, int ntiles) {
    constexpr int XS = CIN + 4;
    extern __shared__ float sm[];
    float* Wsm = sm;               // CIN*64
    float* Xsm = sm + CIN * 64;    // 128*XS
    __shared__ float scl[64], shf[64];
    int t = threadIdx.x;
    int w = t >> 5, lane = t & 31;

    if (BN && t < 64) {
        float mean = stat[t] * invn;
        float var  = stat[64 + t] * invn - mean * mean;
        float sc   = rsqrtf(var + 1e-5f) * gam[t];
        scl[t] = sc;
        shf[t] = bet[t] - mean * sc;
    }

    for (int idx = t; idx < CIN * 64; idx += 256) {
        int o = idx & 63, k = idx >> 6;
        Wsm[k * 64 + o] = __ldg(&W[o * CIN + k]);
    }

    for (int tile = blockIdx.x; tile < ntiles; tile += gridDim.x) {
        __syncthreads();
        int row0 = tile * 128;
        for (int idx = t; idx < 128 * (CIN / 4); idx += 256) {
            int r  = idx / (CIN / 4);
            int c4 = idx % (CIN / 4);
            int gr = row0 + r;
            float4 v = make_float4(0.f, 0.f, 0.f, 0.f);
            if (gr < n) {
                if (sizeof(TIN) == 4) {
                    v = *reinterpret_cast<const float4*>(
                        (const float*)X + (size_t)gr * CIN + c4 * 4);
                } else {
                    const __half2* xh = reinterpret_cast<const __half2*>(
                        (const __half*)X + (size_t)gr * CIN + c4 * 4);
                    float2 p0 = __half22float2(xh[0]);
                    float2 p1 = __half22float2(xh[1]);
                    v = make_float4(p0.x, p0.y, p1.x, p1.y);
                }
            }
            if (BN) {
                int c = c4 * 4;
                v.x = fmaxf(fmaf(v.x, scl[c],     shf[c]),     0.f);
                v.y = fmaxf(fmaf(v.y, scl[c + 1], shf[c + 1]), 0.f);
                v.z = fmaxf(fmaf(v.z, scl[c + 2], shf[c + 2]), 0.f);
                v.w = fmaxf(fmaf(v.w, scl[c + 3], shf[c + 3]), 0.f);
            }
            *reinterpret_cast<float4*>(&Xsm[r * XS + c4 * 4]) = v;
        }
        __syncthreads();

        unsigned long long acc[4][4];
        const float2* b2 = reinterpret_cast<const float2*>(bias);
        #pragma unroll
        for (int p = 0; p < 4; p++) {
            float2 bp = __ldg(&b2[w * 4 + p]);
            unsigned long long bb = pack2(bp.x, bp.y);
            acc[0][p] = bb; acc[1][p] = bb; acc[2][p] = bb; acc[3][p] = bb;
        }

        #pragma unroll 2
        for (int k = 0; k < CIN; k += 4) {
            float4 xr[4];
            #pragma unroll
            for (int rr = 0; rr < 4; rr++)
                xr[rr] = *reinterpret_cast<const float4*>(&Xsm[(lane + rr * 32) * XS + k]);
            #pragma unroll
            for (int kk = 0; kk < 4; kk++) {
                const ulonglong2* wp =
                    reinterpret_cast<const ulonglong2*>(&Wsm[(k + kk) * 64 + w * 8]);
                ulonglong2 wv0 = wp[0];
                ulonglong2 wv1 = wp[1];
                #pragma unroll
                for (int rr = 0; rr < 4; rr++) {
                    unsigned long long pa = pack2s((&xr[rr].x)[kk]);
                    ffma2(acc[rr][0], pa, wv0.x); ffma2(acc[rr][1], pa, wv0.y);
                    ffma2(acc[rr][2], pa, wv1.x); ffma2(acc[rr][3], pa, wv1.y);
                }
            }
        }

        #pragma unroll
        for (int rr = 0; rr < 4; rr++) {
            int gr = row0 + lane + rr * 32;
            if (gr < n) {
                float di = PRESCALE ? __ldg(&dinv[gr]) : 1.0f;
                float a, b;
                __half2 hp[4];
                unpack2(acc[rr][0], a, b); hp[0] = __floats2half2_rn(a * di, b * di);
                unpack2(acc[rr][1], a, b); hp[1] = __floats2half2_rn(a * di, b * di);
                unpack2(acc[rr][2], a, b); hp[2] = __floats2half2_rn(a * di, b * di);
                unpack2(acc[rr][3], a, b); hp[3] = __floats2half2_rn(a * di, b * di);
                *reinterpret_cast<uint4*>(&Yh[(size_t)gr * 64 + w * 8]) =
                    *reinterpret_cast<const uint4*>(hp);
            }
        }
    }
}

// ---------------- aggregation -------------------------------------------------
// RAW:  buffer holds raw Y  -> out_i = dinv_i*(dinv_i*Y_i + sum dinv_j*Y_j)
// else: buffer holds dinv*Y -> out_i = dinv_i*(Y'_i + sum Y'_j)
// STATS: fused BN column stats. LOGSM: fused log_softmax, fp32 out.
template <bool LOGSM, bool STATS, bool RAW>
__global__ __launch_bounds__(256)
void agg_kernel(const __half2* __restrict__ Yh,
                const int* __restrict__ rowptr, const int* __restrict__ csr,
                const float* __restrict__ dinv,
                __half2* __restrict__ outh, float2* __restrict__ outf,
                float* __restrict__ stats, int n) {
    int lane = threadIdx.x & 31;
    int wid  = (blockIdx.x * blockDim.x + threadIdx.x) >> 5;
    int nw   = (gridDim.x * blockDim.x) >> 5;
    float s0 = 0.f, q0 = 0.f, s1 = 0.f, q1 = 0.f;

    for (int i = wid; i < n; i += nw) {
        float di = __ldg(&dinv[i]);
        float2 a = __half22float2(__ldg(&Yh[i * 32 + lane]));
        if (RAW) { a.x *= di; a.y *= di; }
        int s = __ldg(&rowptr[i]);
        int e = __ldg(&rowptr[i + 1]);
        int p = s;
        for (; p + 8 <= e; p += 8) {
            int j[8];
            #pragma unroll
            for (int q = 0; q < 8; q++) j[q] = __ldg(&csr[p + q]);
            float w[8];
            if (RAW) {
                #pragma unroll
                for (int q = 0; q < 8; q++) w[q] = __ldg(&dinv[j[q]]);
            }
            float2 v[8];
            #pragma unroll
            for (int q = 0; q < 8; q++) v[q] = __half22float2(__ldg(&Yh[j[q] * 32 + lane]));
            #pragma unroll
            for (int q = 0; q < 8; q++) {
                if (RAW) {
                    a.x = fmaf(w[q], v[q].x, a.x);
                    a.y = fmaf(w[q], v[q].y, a.y);
                } else {
                    a.x += v[q].x;
                    a.y += v[q].y;
                }
            }
        }
        for (; p < e; p++) {
            int j0 = __ldg(&csr[p]);
            float2 v0 = __half22float2(__ldg(&Yh[j0 * 32 + lane]));
            if (RAW) {
                float w0 = __ldg(&dinv[j0]);
                a.x = fmaf(w0, v0.x, a.x);
                a.y = fmaf(w0, v0.y, a.y);
            } else {
                a.x += v0.x;
                a.y += v0.y;
            }
        }
        a.x *= di;
        a.y *= di;
        if (STATS) {
            s0 += a.x; q0 = fmaf(a.x, a.x, q0);
            s1 += a.y; q1 = fmaf(a.y, a.y, q1);
        }
        if (!LOGSM) {
            outh[i * 32 + lane] = __floats2half2_rn(a.x, a.y);
        } else {
            float m = fmaxf(a.x, a.y);
            #pragma unroll
            for (int o = 16; o > 0; o >>= 1)
                m = fmaxf(m, __shfl_xor_sync(0xFFFFFFFFu, m, o));
            float sum = expf(a.x - m) + expf(a.y - m);
            #pragma unroll
            for (int o = 16; o > 0; o >>= 1)
                sum += __shfl_xor_sync(0xFFFFFFFFu, sum, o);
            float lz = m + logf(sum);
            outf[i * 32 + lane] = make_float2(a.x - lz, a.y - lz);
        }
    }

    if (STATS) {
        __shared__ float4 red[256];
        red[threadIdx.x] = make_float4(s0, q0, s1, q1);
        __syncthreads();
        if (threadIdx.x < 32) {
            float4 r = red[threadIdx.x];
            #pragma unroll
            for (int w = 1; w < 8; w++) {
                float4 o = red[w * 32 + threadIdx.x];
                r.x += o.x; r.y += o.y; r.z += o.z; r.w += o.w;
            }
            atomicAdd(&stats[2 * threadIdx.x],          r.x);
            atomicAdd(&stats[64 + 2 * threadIdx.x],     r.y);
            atomicAdd(&stats[2 * threadIdx.x + 1],      r.z);
            atomicAdd(&stats[64 + 2 * threadIdx.x + 1], r.w);
        }
    }
}

// ---------------- host launcher ----------------
extern "C" void kernel_launch(void* const* d_in, const int* in_sizes, int n_in,
                              void* d_out, int out_size) {
    const float* x   = (const float*)d_in[0];
    const int*   ei  = (const int*)  d_in[1];
    const float* W1  = (const float*)d_in[2];
    const float* b1  = (const float*)d_in[3];
    const float* ga1 = (const float*)d_in[4];
    const float* be1 = (const float*)d_in[5];
    const float* W2  = (const float*)d_in[6];
    const float* b2  = (const float*)d_in[7];
    const float* ga2 = (const float*)d_in[8];
    const float* be2 = (const float*)d_in[9];
    const float* W3  = (const float*)d_in[10];
    const float* b3  = (const float*)d_in[11];
    float* out = (float*)d_out;

    int N = in_sizes[0] / 128;
    int E = in_sizes[1] / 2;
    const int* src = ei;
    const int* dst = ei + E;

    void* p;
    cudaGetSymbolAddress(&p, g_bufA);   __half* bufA  = (__half*)p;
    cudaGetSymbolAddress(&p, g_bufB);   __half* bufB  = (__half*)p;
    cudaGetSymbolAddress(&p, g_csr);    int*   csr    = (int*)p;
    cudaGetSymbolAddress(&p, g_rowptr); int*   rowptr = (int*)p;
    cudaGetSymbolAddress(&p, g_next);   int*   nextp  = (int*)p;
    cudaGetSymbolAddress(&p, g_counts); int*   counts = (int*)p;
    cudaGetSymbolAddress(&p, g_dinv);   float* dinv   = (float*)p;
    cudaGetSymbolAddress(&p, g_stat);   float* stat   = (float*)p;
    cudaGetSymbolAddress(&p, g_bsum);   int*   bsum   = (int*)p;
    cudaGetSymbolAddress(&p, g_boff);   int*   boff   = (int*)p;

    static cudaStream_t sB = nullptr;
    static cudaEvent_t  evF = nullptr, evJ = nullptr;
    if (!sB) {
        cudaStreamCreateWithFlags(&sB, cudaStreamNonBlocking);
        cudaEventCreateWithFlags(&evF, cudaEventDisableTiming);
        cudaEventCreateWithFlags(&evJ, cudaEventDisableTiming);
    }

    const int SMEM1 = (128 * 64 + 128 * 132) * 4;   // 100352 B
    const int SMEM2 = (64 * 64 + 128 * 68) * 4;     // 51200 B
    cudaFuncSetAttribute((const void*)gemm_kernel<128, false, false, float>,
                         cudaFuncAttributeMaxDynamicSharedMemorySize, SMEM1);
    cudaFuncSetAttribute((const void*)gemm_kernel<64, true, true, __half>,
                         cudaFuncAttributeMaxDynamicSharedMemorySize, SMEM2);

    int gridN   = (N + 255) / 256;
    int gridE4  = (E / 4 + 255) / 256;
    int nb      = (N + 1023) / 1024;
    int ntiles  = (N + 127) / 128;
    const int G1   = 296;    // 2 blocks/SM (98KB smem)
    const int G2   = 592;    // 4 blocks/SM (50KB smem)
    const int AGGB = 1184;
    float invn = 1.0f / (float)N;

    const __half2* bufA2 = (const __half2*)bufA;
    __half2* bufB2 = (__half2*)bufB;
    float2*  out2  = (float2*)out;

    // ---- fork: CSR build on sB overlaps GEMM1 (which has no dinv dep) ----
    // Launch-call order chosen so gemm1 is the 4th launch (ncu -s 5 profiles it).
    cudaEventRecord(evF, 0);
    cudaStreamWaitEvent(sB, evF, 0);

    zero_kernel<<<gridN, 256, 0, sB>>>(counts, stat, N);                       // 1
    count_kernel<<<gridE4, 256, 0, sB>>>(dst, counts, E);                      // 2
    bsum_kernel<<<nb, 256, 0, sB>>>(counts, bsum, N);                          // 3
    gemm_kernel<128, false, false, float><<<G1, 256, SMEM1>>>(                 // 4 (profiled)
        x, W1, b1, nullptr, nullptr, nullptr, invn, nullptr, bufA, N, ntiles);
    bscan_kernel<<<1, 128, 0, sB>>>(bsum, boff, rowptr, nb, N, E);             // 5
    scatter_scan_kernel<<<nb, 256, 0, sB>>>(counts, boff, rowptr, nextp, dinv, N); // 6
    fill_kernel<<<gridE4, 256, 0, sB>>>(src, dst, nextp, csr, E);              // 7
    cudaEventRecord(evJ, sB);
    cudaStreamWaitEvent(0, evJ, 0);

    // layer 1 aggregation (applies dinv on both sides per edge)
    agg_kernel<false, true, true><<<AGGB, 256>>>(
        bufA2, rowptr, csr, dinv, bufB2, nullptr, stat, N);

    // layer 2
    gemm_kernel<64, true, true, __half><<<G2, 256, SMEM2>>>(
        bufB, W2, b2, stat, ga1, be1, invn, dinv, bufA, N, ntiles);
    agg_kernel<false, true, false><<<AGGB, 256>>>(
        bufA2, rowptr, csr, dinv, bufB2, nullptr, stat + 128, N);

    // layer 3 + log_softmax
    gemm_kernel<64, true, true, __half><<<G2, 256, SMEM2>>>(
        bufB, W3, b3, stat + 128, ga2, be2, invn, dinv, bufA, N, ntiles);
    agg_kernel<true, false, false><<<AGGB, 256>>>(
        bufA2, rowptr, csr, dinv, nullptr, out2, nullptr, N);
}